// round 12
// baseline (speedup 1.0000x reference)
#include <cuda_runtime.h>
#include <cstdint>

#define D        128
#define DH       32
#define NKP      (D / 2)            // 64 k-pairs
#define P_SEG    16384
#define SEG_PER_BLOCK 16
#define NBLOCKS  (P_SEG / SEG_PER_BLOCK)
#define THREADS  256
#define TILE_M   256
#define KC       32                 // floats per staged chunk (16 k-pairs)
#define KPC      (KC / 2)           // 16 ull per row per chunk
#define NCHUNK   (D / KC)           // 4
#define XROW_ULL 17                 // ull per staged row (16 kp + 1 pad)
#define NROWS_MAX 1000000

__device__ int   g_seg_start[P_SEG + 1];
__device__ float g_e[NROWS_MAX];

typedef unsigned long long ull;

__device__ __forceinline__ ull pack2(float lo, float hi) {
    ull r;
    asm("mov.b64 %0, {%1, %2};" : "=l"(r) : "f"(lo), "f"(hi));
    return r;
}
__device__ __forceinline__ void unpack2(ull v, float& lo, float& hi) {
    asm("mov.b64 {%0, %1}, %2;" : "=f"(lo), "=f"(hi) : "l"(v));
}
// Packed dual-fp32 FMA (FFMA2) — 2x fp32 MAC throughput on sm_103a
__device__ __forceinline__ ull fma2(ull a, ull b, ull c) {
    ull d;
    asm("fma.rn.f32x2 %0, %1, %2, %3;" : "=l"(d) : "l"(a), "l"(b), "l"(c));
    return d;
}
// Single-instruction tanh (MUFU-class). Abs err ~1e-5 -> pooled err << 1e-3.
__device__ __forceinline__ float tanh_fast(float x) {
    float y;
    asm("tanh.approx.f32 %0, %1;" : "=f"(y) : "f"(x));
    return y;
}

// Kernel 1: segment boundaries via binary search over sorted person_ids.
__global__ void seg_bounds_kernel(const int* __restrict__ pids, int n) {
    int p = blockIdx.x * blockDim.x + threadIdx.x;
    if (p > P_SEG) return;
    int lo = 0, hi = n;
    while (lo < hi) {
        int mid = (lo + hi) >> 1;
        if (pids[mid] < p) lo = mid + 1; else hi = mid;
    }
    g_seg_start[p] = lo;
}

// Prefetch one 256-row x 32-float chunk into registers (8 float4 / thread).
__device__ __forceinline__ void ldg_chunk(const float* __restrict__ x,
                                          int tbase, int k0, int rend, int tid,
                                          float4* buf) {
    #pragma unroll
    for (int i = 0; i < 8; ++i) {
        int idx = tid + THREADS * i;
        int row = idx >> 3;          // 0..255
        int kq  = idx & 7;           // float4 within the 32-float chunk
        int r   = tbase + row;
        if (r < rend)
            buf[i] = *(const float4*)(x + r * D + k0 + kq * 4);
        else
            buf[i] = make_float4(0.f, 0.f, 0.f, 0.f);
    }
}

// Kernel 2: fused scores + segment softmax, then weighted pooling pass.
// Thread tile 4 rows x 8 hidden: 32 fma2 per kp-step vs 12 LDS wavefronts
// -> FMA-bound. Double-buffered chunk smem: 1 barrier per chunk.
__global__ __launch_bounds__(THREADS, 2)
void pool_kernel(const float* __restrict__ x, const int* __restrict__ pids,
                 const float* __restrict__ W1, const float* __restrict__ b1,
                 const float* __restrict__ W2, const float* __restrict__ b2,
                 float* __restrict__ out, int has_pids) {
    extern __shared__ float dynsm[];
    ull*   sXA = (ull*)dynsm;                        // [256][17] chunk buffer A
    ull*   sXB = sXA + TILE_M * XROW_ULL;            // [256][17] chunk buffer B
    ull*   sWp = sXB + TILE_M * XROW_ULL;            // [64][32] {W[2k][h],W[2k+1][h]}
    float* sSc = (float*)(sWp + NKP * DH);           // [4][256] per-hg partials
    __shared__ float sW2[DH];
    __shared__ float sB1[DH];
    __shared__ int   sStart[SEG_PER_BLOCK + 1];
    __shared__ float sDen[SEG_PER_BLOCK];

    const int tid  = threadIdx.x;
    const int tx   = tid & 31;     // lane
    const int ty   = tid >> 5;     // warp id
    const int hg   = ty & 3;       // hidden group: hidden [hg*8, hg*8+8)
    const int rg   = ty >> 2;      // row group: rows [rg*128, rg*128+128)
    const int seg0 = blockIdx.x * SEG_PER_BLOCK;

    if (tid <= SEG_PER_BLOCK) sStart[tid] = g_seg_start[seg0 + tid];
    if (tid < DH) { sW2[tid] = W2[tid]; sB1[tid] = b1[tid]; }
    if (tid < SEG_PER_BLOCK) sDen[tid] = 0.f;
    for (int i = tid; i < NKP * DH; i += THREADS) {
        int kp = i >> 5, h = i & 31;
        sWp[i] = pack2(W1[(2 * kp) * DH + h], W1[(2 * kp + 1) * DH + h]);
    }
    const float b2v = b2[0];
    __syncthreads();

    const int rbeg = sStart[0], rend = sStart[SEG_PER_BLOCK];
    const int nTiles = (rend - rbeg + TILE_M - 1) / TILE_M;

    float4 buf[8];
    if (nTiles > 0) ldg_chunk(x, rbeg, 0, rend, tid, buf);

    const int row0 = rg * 128 + tx;   // rows: row0 + 32j, j = 0..3

    // ---- Phase A: register-blocked score GEMM + exp + shared denom ----
    for (int t = 0; t < nTiles; ++t) {
        const int tbase = rbeg + t * TILE_M;
        ull acc[4][8];
        #pragma unroll
        for (int j = 0; j < 4; ++j)
            #pragma unroll
            for (int jh = 0; jh < 8; ++jh) acc[j][jh] = 0ULL;

        for (int c = 0; c < NCHUNK; ++c) {
            ull* sbuf = (c & 1) ? sXB : sXA;
            // stage chunk c from prefetch regs. Writes buffer (c&1); any warp
            // still computing chunk c-1 reads the OTHER buffer, and chunk c-2's
            // readers are behind the previous barrier -> no pre-barrier needed.
            #pragma unroll
            for (int i = 0; i < 8; ++i) {
                int idx = tid + THREADS * i;
                int row = idx >> 3;
                int kq  = idx & 7;
                float2* dst = (float2*)(sbuf + row * XROW_ULL + kq * 2);
                dst[0] = make_float2(buf[i].x, buf[i].y);
                dst[1] = make_float2(buf[i].z, buf[i].w);
            }
            __syncthreads();
            // prefetch next chunk (next k-chunk, or next tile's chunk 0)
            int nc = c + 1, nb = tbase;
            if (nc == NCHUNK) { nc = 0; nb += TILE_M; }
            if (nb < rend) ldg_chunk(x, nb, nc * KC, rend, tid, buf);

            // compute: 16 kp-steps x 32 fma2 per thread
            const int kp0 = c * KPC;
            #pragma unroll 4
            for (int kk = 0; kk < KPC; ++kk) {
                ull xp0 = sbuf[(row0      ) * XROW_ULL + kk];
                ull xp1 = sbuf[(row0 + 32 ) * XROW_ULL + kk];
                ull xp2 = sbuf[(row0 + 64 ) * XROW_ULL + kk];
                ull xp3 = sbuf[(row0 + 96 ) * XROW_ULL + kk];
                const ulonglong2* wr =
                    (const ulonglong2*)(sWp + (kp0 + kk) * DH + hg * 8);
                ulonglong2 wa = wr[0], wb = wr[1], wc = wr[2], wd = wr[3];
                acc[0][0] = fma2(xp0, wa.x, acc[0][0]);
                acc[0][1] = fma2(xp0, wa.y, acc[0][1]);
                acc[0][2] = fma2(xp0, wb.x, acc[0][2]);
                acc[0][3] = fma2(xp0, wb.y, acc[0][3]);
                acc[0][4] = fma2(xp0, wc.x, acc[0][4]);
                acc[0][5] = fma2(xp0, wc.y, acc[0][5]);
                acc[0][6] = fma2(xp0, wd.x, acc[0][6]);
                acc[0][7] = fma2(xp0, wd.y, acc[0][7]);
                acc[1][0] = fma2(xp1, wa.x, acc[1][0]);
                acc[1][1] = fma2(xp1, wa.y, acc[1][1]);
                acc[1][2] = fma2(xp1, wb.x, acc[1][2]);
                acc[1][3] = fma2(xp1, wb.y, acc[1][3]);
                acc[1][4] = fma2(xp1, wc.x, acc[1][4]);
                acc[1][5] = fma2(xp1, wc.y, acc[1][5]);
                acc[1][6] = fma2(xp1, wd.x, acc[1][6]);
                acc[1][7] = fma2(xp1, wd.y, acc[1][7]);
                acc[2][0] = fma2(xp2, wa.x, acc[2][0]);
                acc[2][1] = fma2(xp2, wa.y, acc[2][1]);
                acc[2][2] = fma2(xp2, wb.x, acc[2][2]);
                acc[2][3] = fma2(xp2, wb.y, acc[2][3]);
                acc[2][4] = fma2(xp2, wc.x, acc[2][4]);
                acc[2][5] = fma2(xp2, wc.y, acc[2][5]);
                acc[2][6] = fma2(xp2, wd.x, acc[2][6]);
                acc[2][7] = fma2(xp2, wd.y, acc[2][7]);
                acc[3][0] = fma2(xp3, wa.x, acc[3][0]);
                acc[3][1] = fma2(xp3, wa.y, acc[3][1]);
                acc[3][2] = fma2(xp3, wb.x, acc[3][2]);
                acc[3][3] = fma2(xp3, wb.y, acc[3][3]);
                acc[3][4] = fma2(xp3, wc.x, acc[3][4]);
                acc[3][5] = fma2(xp3, wc.y, acc[3][5]);
                acc[3][6] = fma2(xp3, wd.x, acc[3][6]);
                acc[3][7] = fma2(xp3, wd.y, acc[3][7]);
            }
        }

        // partial scores: tanh + W2 over this thread's 8 hidden, per row.
        // lo+hi collapses the even/odd-k subsums.
        #pragma unroll
        for (int j = 0; j < 4; ++j) {
            float s = 0.f;
            #pragma unroll
            for (int jh = 0; jh < 8; ++jh) {
                int h = hg * 8 + jh;
                float lo, hi;
                unpack2(acc[j][jh], lo, hi);
                s += tanh_fast(lo + hi + sB1[h]) * sW2[h];
            }
            sSc[hg * TILE_M + row0 + 32 * j] = s;   // plain store, no atomics
        }
        __syncthreads();

        // finalize: one thread per row. |score| <= ~6 analytically, exp safe.
        {
            int row = tbase + tid;
            if (row < rend) {
                float sc = sSc[tid] + sSc[TILE_M + tid] +
                           sSc[2 * TILE_M + tid] + sSc[3 * TILE_M + tid] + b2v;
                float e = __expf(sc);
                g_e[row] = e;
                atomicAdd(&sDen[pids[row] - seg0], e);
            }
        }
        // no barrier needed: next tile's sSc writes are >= 4 barriers away,
        // and chunk staging touches disjoint buffers.
    }
    __syncthreads();

    // ---- Phase B: weighted pooling; warp ty handles segments ty, ty+8 ----
    // (rows are L2-resident from Phase A's recent pass within the wave)
    for (int s = ty; s < SEG_PER_BLOCK; s += 8) {
        const int a = sStart[s], bnd = sStart[s + 1];
        const float den  = sDen[s];
        const float dinv = den > 0.f ? 1.f / den : 0.f;
        float4 acc4 = make_float4(0.f, 0.f, 0.f, 0.f);
        #pragma unroll 8
        for (int r = a; r < bnd; ++r) {
            float w = g_e[r] * dinv;
            float4 xv = *(const float4*)(x + r * D + tx * 4);
            acc4.x = fmaf(w, xv.x, acc4.x);
            acc4.y = fmaf(w, xv.y, acc4.y);
            acc4.z = fmaf(w, xv.z, acc4.z);
            acc4.w = fmaf(w, xv.w, acc4.w);
        }
        *(float4*)(out + (seg0 + s) * D + tx * 4) = acc4;
    }

    // ---- pooled_pids tail (arange), if the output buffer includes it ----
    if (has_pids && tid < SEG_PER_BLOCK) {
        out[P_SEG * D + seg0 + tid] = (float)(seg0 + tid);
    }
}

extern "C" void kernel_launch(void* const* d_in, const int* in_sizes, int n_in,
                              void* d_out, int out_size) {
    const float* x   = (const float*)d_in[0];
    const int*   pid = (const int*)d_in[1];
    const float* W1  = (const float*)d_in[2];
    const float* b1  = (const float*)d_in[3];
    const float* W2  = (const float*)d_in[4];
    const float* b2  = (const float*)d_in[5];
    const int n = in_sizes[1];
    const int has_pids = (out_size >= P_SEG * D + P_SEG) ? 1 : 0;

    seg_bounds_kernel<<<(P_SEG + 1 + 255) / 256, 256>>>(pid, n);

    const int smem_bytes = 2 * TILE_M * XROW_ULL * 8   // sXA + sXB
                         + NKP * DH * 8                // sWp
                         + 4 * TILE_M * 4;             // sSc
    cudaFuncSetAttribute((const void*)pool_kernel,
                         cudaFuncAttributeMaxDynamicSharedMemorySize,
                         smem_bytes);
    pool_kernel<<<NBLOCKS, THREADS, smem_bytes>>>(
        x, pid, W1, b1, W2, b2, (float*)d_out, has_pids);
}

// round 16
// speedup vs baseline: 1.5475x; 1.5475x over previous
#include <cuda_runtime.h>
#include <cuda_bf16.h>
#include <cstdint>

#define D        128
#define DH       32
#define P_SEG    16384
#define SEG_PER_BLOCK 16
#define NBLOCKS  (P_SEG / SEG_PER_BLOCK)
#define THREADS  256
#define TILE_M   128
#define KC       32
#define NCHUNK   (D / KC)       // 4
#define NROWS_MAX 1000000

// smem layout (bytes). 40 bf16 = 80B padded rows -> ldmatrix conflict-free.
#define ROWB     80
#define OFF_AH   0              // A hi: 128 rows x 80B (chunk of 32 k)
#define OFF_AL   10240          // A lo
#define OFF_WH   20480          // W hi: 128 k-rows x 80B (32 h + pad)
#define OFF_WL   30720          // W lo
#define SMEM_BYTES 40960

__device__ int   g_seg_start[P_SEG + 1];
__device__ float g_e[NROWS_MAX];

// ---------------- helpers ----------------
__device__ __forceinline__ uint32_t smem_u32(const void* p) {
    uint32_t a;
    asm("{ .reg .u64 t; cvta.to.shared.u64 t, %1; cvt.u32.u64 %0, t; }"
        : "=r"(a) : "l"(p));
    return a;
}
__device__ __forceinline__ void ldm_x4(uint32_t* r, uint32_t addr) {
    asm volatile("ldmatrix.sync.aligned.m8n8.x4.shared.b16 {%0,%1,%2,%3}, [%4];"
                 : "=r"(r[0]), "=r"(r[1]), "=r"(r[2]), "=r"(r[3]) : "r"(addr));
}
__device__ __forceinline__ void ldm_x4t(uint32_t* r, uint32_t addr) {
    asm volatile("ldmatrix.sync.aligned.m8n8.x4.trans.shared.b16 {%0,%1,%2,%3}, [%4];"
                 : "=r"(r[0]), "=r"(r[1]), "=r"(r[2]), "=r"(r[3]) : "r"(addr));
}
// D += A(16x16 bf16,row) @ B(16x8 bf16,col)
__device__ __forceinline__ void mma_bf16(float* d, const uint32_t* a,
                                         const uint32_t* b) {
    asm volatile(
        "mma.sync.aligned.m16n8k16.row.col.f32.bf16.bf16.f32 "
        "{%0,%1,%2,%3}, {%4,%5,%6,%7}, {%8,%9}, {%0,%1,%2,%3};"
        : "+f"(d[0]), "+f"(d[1]), "+f"(d[2]), "+f"(d[3])
        : "r"(a[0]), "r"(a[1]), "r"(a[2]), "r"(a[3]), "r"(b[0]), "r"(b[1]));
}
__device__ __forceinline__ void sts_v2(uint32_t addr, uint32_t a, uint32_t b) {
    asm volatile("st.shared.v2.b32 [%0], {%1, %2};" :: "r"(addr), "r"(a), "r"(b)
                 : "memory");
}
__device__ __forceinline__ void sts_b16(uint32_t addr, uint16_t v) {
    asm volatile("st.shared.b16 [%0], %1;" :: "r"(addr), "h"(v) : "memory");
}
__device__ __forceinline__ uint32_t cvt_bf16x2(float hi, float lo) {
    uint32_t r;  // {lo16 = bf16(lo), hi16 = bf16(hi)}
    asm("cvt.rn.bf16x2.f32 %0, %1, %2;" : "=r"(r) : "f"(hi), "f"(lo));
    return r;
}
__device__ __forceinline__ float tanh_fast(float x) {
    float y;
    asm("tanh.approx.f32 %0, %1;" : "=f"(y) : "f"(x));
    return y;
}

// Kernel 1: segment boundaries via binary search over sorted person_ids.
__global__ void seg_bounds_kernel(const int* __restrict__ pids, int n) {
    int p = blockIdx.x * blockDim.x + threadIdx.x;
    if (p > P_SEG) return;
    int lo = 0, hi = n;
    while (lo < hi) {
        int mid = (lo + hi) >> 1;
        if (pids[mid] < p) lo = mid + 1; else hi = mid;
    }
    g_seg_start[p] = lo;
}

// Prefetch one 128-row x 32-float chunk into registers (4 float4 / thread).
__device__ __forceinline__ void ldg_chunk(const float* __restrict__ x,
                                          int tbase, int k0, int rend, int tid,
                                          float4* buf) {
    #pragma unroll
    for (int i = 0; i < 4; ++i) {
        int idx = tid + THREADS * i;
        int row = idx >> 3;          // 0..127
        int kq  = idx & 7;           // float4 within 32-float chunk
        int r   = tbase + row;
        if (r < rend)
            buf[i] = *(const float4*)(x + r * D + k0 + kq * 4);
        else
            buf[i] = make_float4(0.f, 0.f, 0.f, 0.f);
    }
}

// Kernel 2: HMMA (mma.sync bf16 split-precision) score GEMM + softmax,
// then weighted pooling pass. Warp w owns rows [w*16, w*16+16).
__global__ __launch_bounds__(THREADS)
void pool_kernel(const float* __restrict__ x, const int* __restrict__ pids,
                 const float* __restrict__ W1, const float* __restrict__ b1,
                 const float* __restrict__ W2, const float* __restrict__ b2,
                 float* __restrict__ out, int has_pids) {
    __shared__ __align__(16) char sData[SMEM_BYTES];
    __shared__ int   sStart[SEG_PER_BLOCK + 1];
    __shared__ float sDen[SEG_PER_BLOCK];

    const int tid  = threadIdx.x;
    const int lane = tid & 31;
    const int w    = tid >> 5;
    const int seg0 = blockIdx.x * SEG_PER_BLOCK;
    const uint32_t sbase = smem_u32(sData);

    if (tid <= SEG_PER_BLOCK) sStart[tid] = g_seg_start[seg0 + tid];
    if (tid < SEG_PER_BLOCK) sDen[tid] = 0.f;

    // Stage W1 split halves: [k][h] row-major, 80B row stride.
    for (int i = tid; i < D * DH; i += THREADS) {
        int k = i >> 5, h = i & 31;
        float wv = W1[i];
        __nv_bfloat16 bh = __float2bfloat16(wv);
        uint16_t hb; { hb = *(uint16_t*)&bh; }
        float hf = __uint_as_float(((uint32_t)hb) << 16);
        __nv_bfloat16 bl = __float2bfloat16(wv - hf);
        uint16_t lb; { lb = *(uint16_t*)&bl; }
        uint32_t off = (uint32_t)(k * ROWB + h * 2);
        sts_b16(sbase + OFF_WH + off, hb);
        sts_b16(sbase + OFF_WL + off, lb);
    }

    // Per-thread epilogue coefficients: h = nt*8 + (lane&3)*2 + j
    float w2r[8], b1r[8];
    {
        int h0 = (lane & 3) * 2;
        #pragma unroll
        for (int nt = 0; nt < 4; ++nt) {
            w2r[nt * 2 + 0] = W2[nt * 8 + h0 + 0];
            w2r[nt * 2 + 1] = W2[nt * 8 + h0 + 1];
            b1r[nt * 2 + 0] = b1[nt * 8 + h0 + 0];
            b1r[nt * 2 + 1] = b1[nt * 8 + h0 + 1];
        }
    }
    const float b2v = b2[0];
    __syncthreads();

    const int rbeg = sStart[0], rend = sStart[SEG_PER_BLOCK];
    const int nTiles = (rend - rbeg + TILE_M - 1) / TILE_M;

    float4 buf[4];
    if (nTiles > 0) ldg_chunk(x, rbeg, 0, rend, tid, buf);

    // ldmatrix lane address components (16B-granular, conflict-free rows)
    const uint32_t laneA = (uint32_t)((lane & 15) * ROWB + (lane >> 4) * 16);
    const uint32_t aHbase = sbase + OFF_AH + (uint32_t)(w * 16 * ROWB) + laneA;
    const uint32_t aLbase = sbase + OFF_AL + (uint32_t)(w * 16 * ROWB) + laneA;
    const uint32_t wHbase = sbase + OFF_WH + laneA;   // k-row addressing
    const uint32_t wLbase = sbase + OFF_WL + laneA;

    // ---- Phase A ----
    for (int t = 0; t < nTiles; ++t) {
        const int tbase = rbeg + t * TILE_M;
        float acc[4][4];
        #pragma unroll
        for (int nt = 0; nt < 4; ++nt)
            #pragma unroll
            for (int j = 0; j < 4; ++j) acc[nt][j] = 0.f;

        for (int c = 0; c < NCHUNK; ++c) {
            __syncthreads();   // prior compute done reading A chunk
            // stage chunk: convert fp32 -> bf16 hi/lo, 80B rows
            #pragma unroll
            for (int i = 0; i < 4; ++i) {
                int idx = tid + THREADS * i;
                int row = idx >> 3;
                int kq  = idx & 7;
                float4 v = buf[i];
                uint32_t h01 = cvt_bf16x2(v.y, v.x);
                uint32_t h23 = cvt_bf16x2(v.w, v.z);
                float r0 = v.x - __uint_as_float(h01 << 16);
                float r1 = v.y - __uint_as_float(h01 & 0xFFFF0000u);
                float r2 = v.z - __uint_as_float(h23 << 16);
                float r3 = v.w - __uint_as_float(h23 & 0xFFFF0000u);
                uint32_t l01 = cvt_bf16x2(r1, r0);
                uint32_t l23 = cvt_bf16x2(r3, r2);
                uint32_t off = (uint32_t)(row * ROWB + kq * 8);
                sts_v2(sbase + OFF_AH + off, h01, h23);
                sts_v2(sbase + OFF_AL + off, l01, l23);
            }
            __syncthreads();
            // prefetch next chunk (or next tile's chunk 0)
            int nc = c + 1, nb = tbase;
            if (nc == NCHUNK) { nc = 0; nb += TILE_M; }
            if (nb < rend) ldg_chunk(x, nb, nc * KC, rend, tid, buf);

            // compute: 2 k16-steps
            #pragma unroll
            for (int ks = 0; ks < 2; ++ks) {
                uint32_t ah[4], al[4], bh0[4], bh1[4], bl0[4], bl1[4];
                ldm_x4(ah, aHbase + ks * 32);
                ldm_x4(al, aLbase + ks * 32);
                uint32_t wk = (uint32_t)((c * KC + ks * 16) * ROWB);
                ldm_x4t(bh0, wHbase + wk);        // n-tiles 0,1
                ldm_x4t(bh1, wHbase + wk + 32);   // n-tiles 2,3
                ldm_x4t(bl0, wLbase + wk);
                ldm_x4t(bl1, wLbase + wk + 32);
                // xh@wh
                mma_bf16(acc[0], ah, bh0);
                mma_bf16(acc[1], ah, bh0 + 2);
                mma_bf16(acc[2], ah, bh1);
                mma_bf16(acc[3], ah, bh1 + 2);
                // xh@wl
                mma_bf16(acc[0], ah, bl0);
                mma_bf16(acc[1], ah, bl0 + 2);
                mma_bf16(acc[2], ah, bl1);
                mma_bf16(acc[3], ah, bl1 + 2);
                // xl@wh
                mma_bf16(acc[0], al, bh0);
                mma_bf16(acc[1], al, bh0 + 2);
                mma_bf16(acc[2], al, bh1);
                mma_bf16(acc[3], al, bh1 + 2);
            }
        }

        // epilogue: tanh + W2, quad-reduce, e + denom. Rows: w*16+g, +8.
        float sp0 = 0.f, sp1 = 0.f;
        #pragma unroll
        for (int nt = 0; nt < 4; ++nt) {
            #pragma unroll
            for (int j = 0; j < 2; ++j) {
                sp0 += tanh_fast(acc[nt][j]     + b1r[nt * 2 + j]) * w2r[nt * 2 + j];
                sp1 += tanh_fast(acc[nt][2 + j] + b1r[nt * 2 + j]) * w2r[nt * 2 + j];
            }
        }
        sp0 += __shfl_xor_sync(0xFFFFFFFFu, sp0, 1);
        sp0 += __shfl_xor_sync(0xFFFFFFFFu, sp0, 2);
        sp1 += __shfl_xor_sync(0xFFFFFFFFu, sp1, 1);
        sp1 += __shfl_xor_sync(0xFFFFFFFFu, sp1, 2);
        if ((lane & 3) == 0) {
            int r0 = tbase + w * 16 + (lane >> 2);
            if (r0 < rend) {
                float e = __expf(sp0 + b2v);   // |score| <= ~6 analytically
                g_e[r0] = e;
                atomicAdd(&sDen[pids[r0] - seg0], e);
            }
            int r1 = r0 + 8;
            if (r1 < rend) {
                float e = __expf(sp1 + b2v);
                g_e[r1] = e;
                atomicAdd(&sDen[pids[r1] - seg0], e);
            }
        }
    }
    __syncthreads();

    // ---- Phase B: weighted pooling; warp w handles segments w, w+8 ----
    for (int s = w; s < SEG_PER_BLOCK; s += 8) {
        const int a = sStart[s], bnd = sStart[s + 1];
        const float den  = sDen[s];
        const float dinv = den > 0.f ? 1.f / den : 0.f;
        float4 acc4 = make_float4(0.f, 0.f, 0.f, 0.f);
        #pragma unroll 8
        for (int r = a; r < bnd; ++r) {
            float wv = g_e[r] * dinv;
            float4 xv = *(const float4*)(x + r * D + lane * 4);
            acc4.x = fmaf(wv, xv.x, acc4.x);
            acc4.y = fmaf(wv, xv.y, acc4.y);
            acc4.z = fmaf(wv, xv.z, acc4.z);
            acc4.w = fmaf(wv, xv.w, acc4.w);
        }
        *(float4*)(out + (seg0 + s) * D + lane * 4) = acc4;
    }

    // ---- pooled_pids tail (arange), if the output buffer includes it ----
    if (has_pids && tid < SEG_PER_BLOCK)
        out[P_SEG * D + seg0 + tid] = (float)(seg0 + tid);
}

extern "C" void kernel_launch(void* const* d_in, const int* in_sizes, int n_in,
                              void* d_out, int out_size) {
    const float* x   = (const float*)d_in[0];
    const int*   pid = (const int*)d_in[1];
    const float* W1  = (const float*)d_in[2];
    const float* b1  = (const float*)d_in[3];
    const float* W2  = (const float*)d_in[4];
    const float* b2  = (const float*)d_in[5];
    const int n = in_sizes[1];
    const int has_pids = (out_size >= P_SEG * D + P_SEG) ? 1 : 0;

    seg_bounds_kernel<<<(P_SEG + 1 + 255) / 256, 256>>>(pid, n);

    pool_kernel<<<NBLOCKS, THREADS>>>(
        x, pid, W1, b1, W2, b2, (float*)d_out, has_pids);
}